// round 2
// baseline (speedup 1.0000x reference)
#include <cuda_runtime.h>
#include <cuda_bf16.h>
#include <cstdint>

// Problem constants
constexpr int S = 256, B = 128, E = 256, H = 512, T = 18;
constexpr int SB = S * B;          // 32768
constexpr int G4H = 4 * H;         // 2048
constexpr int H2 = 2 * H;          // 1024

// ---------------- scratch (static device globals; no allocation) ------------
__device__ float d_x0[SB * E];            // embedded input  [SB, E]
__device__ float d_xpf[(size_t)SB * G4H]; // forward input projection [SB, 4H]
__device__ float d_xpb[(size_t)SB * G4H]; // backward input projection
__device__ float d_seq0[(size_t)SB * H2]; // layer-0 output [SB, 2H]
__device__ float d_seq1[(size_t)SB * H2]; // layer-1 output
__device__ float d_fc[(size_t)SB * H];    // fc output [SB, H]
__device__ float d_emis[(size_t)SB * T];  // emissions [SB, T]
__device__ float d_hbuf[2][2 * B * H];    // h double buffer: [buf][dir*B*H + ...]
__device__ float d_cst[2 * B * H];        // c state per dir
__device__ float d_llh[B];

// ---------------- helpers ---------------------------------------------------
__device__ __forceinline__ float sigm(float x) { return 1.f / (1.f + expf(-x)); }

// ---------------- embedding: x0[s*B+b][:] = (id? emb[id] : 0) ---------------
__global__ void embed_kernel(const int* __restrict__ ids, const float* __restrict__ emb)
{
    int row = blockIdx.x;            // = s*B + b
    int s = row / B, b = row - s * B;
    int id = ids[b * S + s];
    float4* dst = reinterpret_cast<float4*>(&d_x0[(size_t)row * E]);
    int e = threadIdx.x;             // 64 threads, E/4 = 64 float4
    if (id == 0) dst[e] = make_float4(0.f, 0.f, 0.f, 0.f);
    else dst[e] = reinterpret_cast<const float4*>(&emb[(size_t)id * E])[e];
}

// ---------------- SGEMM: C[M,N] = A[M,K] @ W[N,K]^T + bias, optional relu ---
// 128x128 tile, BK=8, 256 threads, 8x8 microtile, reg-staged prefetch.
__global__ void __launch_bounds__(256) sgemm_kernel(
    const float* __restrict__ A, const float* __restrict__ W,
    const float* __restrict__ bias, float* __restrict__ C,
    int M, int N, int K, int relu)
{
    __shared__ float As[8][128];
    __shared__ float Ws[8][128];
    int bm = blockIdx.y * 128, bn = blockIdx.x * 128;
    int tid = threadIdx.x;
    int lr = tid >> 1;               // 0..127 tile row
    int ls = (tid & 1) * 4;          // 0 or 4 (k-seg)
    int tx = tid & 15, ty = tid >> 4;

    const float* Ap = A + (size_t)(bm + lr) * K + ls;
    const float* Wp = W + (size_t)(bn + lr) * K + ls;

    float4 a_ld = *reinterpret_cast<const float4*>(Ap);
    float4 w_ld = *reinterpret_cast<const float4*>(Wp);

    float acc[8][8] = {};

    for (int k0 = 0; k0 < K; k0 += 8) {
        As[ls + 0][lr] = a_ld.x; As[ls + 1][lr] = a_ld.y;
        As[ls + 2][lr] = a_ld.z; As[ls + 3][lr] = a_ld.w;
        Ws[ls + 0][lr] = w_ld.x; Ws[ls + 1][lr] = w_ld.y;
        Ws[ls + 2][lr] = w_ld.z; Ws[ls + 3][lr] = w_ld.w;
        __syncthreads();
        if (k0 + 8 < K) {
            a_ld = *reinterpret_cast<const float4*>(Ap + k0 + 8);
            w_ld = *reinterpret_cast<const float4*>(Wp + k0 + 8);
        }
#pragma unroll
        for (int k = 0; k < 8; k++) {
            float4 a0 = *reinterpret_cast<const float4*>(&As[k][ty * 8]);
            float4 a1 = *reinterpret_cast<const float4*>(&As[k][ty * 8 + 4]);
            float4 b0 = *reinterpret_cast<const float4*>(&Ws[k][tx * 8]);
            float4 b1 = *reinterpret_cast<const float4*>(&Ws[k][tx * 8 + 4]);
            float a[8] = {a0.x, a0.y, a0.z, a0.w, a1.x, a1.y, a1.z, a1.w};
            float b[8] = {b0.x, b0.y, b0.z, b0.w, b1.x, b1.y, b1.z, b1.w};
#pragma unroll
            for (int i = 0; i < 8; i++)
#pragma unroll
                for (int j = 0; j < 8; j++)
                    acc[i][j] += a[i] * b[j];
        }
        __syncthreads();
    }

    float bv[8];
#pragma unroll
    for (int j = 0; j < 8; j++) bv[j] = bias[bn + tx * 8 + j];

#pragma unroll
    for (int i = 0; i < 8; i++) {
        int row = bm + ty * 8 + i;
        float v[8];
#pragma unroll
        for (int j = 0; j < 8; j++) {
            v[j] = acc[i][j] + bv[j];
            if (relu) v[j] = fmaxf(v[j], 0.f);
        }
        float4* dst = reinterpret_cast<float4*>(&C[(size_t)row * N + bn + tx * 8]);
        dst[0] = make_float4(v[0], v[1], v[2], v[3]);
        dst[1] = make_float4(v[4], v[5], v[6], v[7]);
    }
}

// ---------------- zero h/c states -------------------------------------------
__global__ void zero_states_kernel()
{
    int i = blockIdx.x * 256 + threadIdx.x;
    if (i < 2 * B * H) {
        d_hbuf[0][i] = 0.f;
        d_hbuf[1][i] = 0.f;
        d_cst[i] = 0.f;
    }
}

// ---------------- fused LSTM step (both directions) -------------------------
// grid: (H/8, 2), 256 threads. Each block: 8 hidden cols x 4 gates x all B,
// GEMM over K=H from h_in, then pointwise, writes h_out / c / seq.
__global__ void __launch_bounds__(256) lstm_step_kernel(
    const float* __restrict__ xpf, const float* __restrict__ xpb,
    const float* __restrict__ wf,  const float* __restrict__ wb,
    const float* __restrict__ hin, float* __restrict__ hout,
    float* __restrict__ cst, float* __restrict__ seq, int t)
{
    __shared__ float Hs[32][128];   // h chunk, k-major
    __shared__ float Ws[32][32];    // weight chunk, k-major
    int dir = blockIdx.y;
    int n0 = blockIdx.x * 8;
    int tt = dir ? (S - 1 - t) : t;
    const float* xp = dir ? xpb : xpf;
    const float* w  = dir ? wb : wf;
    const float* h  = hin  + dir * (B * H);
    float* hn       = hout + dir * (B * H);
    float* c        = cst  + dir * (B * H);

    int tid = threadIdx.x;
    int tx = tid & 15, ty = tid >> 4;
    int wnc = tid >> 3, wseg = tid & 7;                 // 32 cols x 8 segs
    int wr  = (wnc >> 3) * H + n0 + (wnc & 7);          // gate row in W_hh
    const float* wrow = w + (size_t)wr * H;

    float acc[8][2] = {};

    for (int k0 = 0; k0 < H; k0 += 32) {
        // stage h[0:128][k0:k0+32] -> Hs (k-major)
#pragma unroll
        for (int i = 0; i < 4; i++) {
            int e = tid + i * 256;
            int m = e >> 3, seg = e & 7;
            float4 v = *reinterpret_cast<const float4*>(&h[m * H + k0 + seg * 4]);
            Hs[seg * 4 + 0][m] = v.x; Hs[seg * 4 + 1][m] = v.y;
            Hs[seg * 4 + 2][m] = v.z; Hs[seg * 4 + 3][m] = v.w;
        }
        {
            float4 v = *reinterpret_cast<const float4*>(&wrow[k0 + wseg * 4]);
            Ws[wseg * 4 + 0][wnc] = v.x; Ws[wseg * 4 + 1][wnc] = v.y;
            Ws[wseg * 4 + 2][wnc] = v.z; Ws[wseg * 4 + 3][wnc] = v.w;
        }
        __syncthreads();
#pragma unroll
        for (int k = 0; k < 32; k++) {
            float4 a0 = *reinterpret_cast<const float4*>(&Hs[k][ty * 8]);
            float4 a1 = *reinterpret_cast<const float4*>(&Hs[k][ty * 8 + 4]);
            float b0 = Ws[k][tx * 2], b1 = Ws[k][tx * 2 + 1];
            float a[8] = {a0.x, a0.y, a0.z, a0.w, a1.x, a1.y, a1.z, a1.w};
#pragma unroll
            for (int i = 0; i < 8; i++) {
                acc[i][0] += a[i] * b0;
                acc[i][1] += a[i] * b1;
            }
        }
        __syncthreads();
    }

    // gates to shared (reuse Hs storage as Gs[128][32]), adding xp
    float* Gs = &Hs[0][0];
#pragma unroll
    for (int i = 0; i < 8; i++) {
        int m = ty * 8 + i;
#pragma unroll
        for (int j = 0; j < 2; j++) {
            int nc = tx * 2 + j;
            int r = (nc >> 3) * H + n0 + (nc & 7);
            Gs[m * 32 + nc] = acc[i][j] + xp[((size_t)tt * B + m) * G4H + r];
        }
    }
    __syncthreads();

    // pointwise LSTM for 128 rows x 8 hidden cols
    for (int e = tid; e < B * 8; e += 256) {
        int m = e >> 3, j = e & 7;
        float ig = Gs[m * 32 + j];
        float fg = Gs[m * 32 + 8 + j];
        float gg = Gs[m * 32 + 16 + j];
        float og = Gs[m * 32 + 24 + j];
        int idx = m * H + n0 + j;
        float cv = c[idx];
        float cn = sigm(fg) * cv + sigm(ig) * tanhf(gg);
        float hv = sigm(og) * tanhf(cn);
        c[idx] = cn;
        hn[idx] = hv;
        seq[((size_t)tt * B + m) * H2 + dir * H + n0 + j] = hv;
    }
}

// ---------------- classifier: emissions = fc @ cls_w^T + cls_b --------------
__global__ void cls_kernel(const float* __restrict__ clsw, const float* __restrict__ clsb)
{
    __shared__ float hrow[H];
    int row = blockIdx.x;
    int tid = threadIdx.x;   // 256
    reinterpret_cast<float2*>(hrow)[tid] =
        reinterpret_cast<const float2*>(&d_fc[(size_t)row * H])[tid];
    __syncthreads();
    int warp = tid >> 5, lane = tid & 31;
    for (int tg = warp; tg < T; tg += 8) {
        const float* wv = clsw + tg * H;
        float s = 0.f;
        for (int k = lane; k < H; k += 32) s += hrow[k] * wv[k];
#pragma unroll
        for (int o = 16; o; o >>= 1) s += __shfl_down_sync(0xffffffffu, s, o);
        if (lane == 0) d_emis[(size_t)row * T + tg] = s + clsb[tg];
    }
}

// ---------------- CRF: one block per batch, numerator + forward algorithm ---
__global__ void crf_kernel(const int* __restrict__ ids, const int* __restrict__ tags,
                           const float* __restrict__ trans,
                           const float* __restrict__ st, const float* __restrict__ en)
{
    __shared__ float Tr[T * T];
    __shared__ float alpha[T];
    int b = blockIdx.x;
    int tid = threadIdx.x;   // 32
    for (int i = tid; i < T * T; i += 32) Tr[i] = trans[i];
    __syncthreads();

    if (tid < T) alpha[tid] = st[tid] + d_emis[(size_t)(0 * B + b) * T + tid];
    __syncthreads();
    for (int s = 1; s < S; s++) {
        bool msk = ids[b * S + s] != 0;
        float ns = 0.f;
        if (tid < T) {
            float mx = -1e30f;
#pragma unroll
            for (int i = 0; i < T; i++) mx = fmaxf(mx, alpha[i] + Tr[i * T + tid]);
            float sum = 0.f;
#pragma unroll
            for (int i = 0; i < T; i++) sum += expf(alpha[i] + Tr[i * T + tid] - mx);
            ns = mx + logf(sum) + d_emis[(size_t)(s * B + b) * T + tid];
        }
        __syncthreads();
        if (tid < T && msk) alpha[tid] = ns;
        __syncthreads();
    }

    if (tid == 0) {
        float mx = -1e30f;
        for (int i = 0; i < T; i++) mx = fmaxf(mx, alpha[i] + en[i]);
        float sum = 0.f;
        for (int i = 0; i < T; i++) sum += expf(alpha[i] + en[i] - mx);
        float denom = mx + logf(sum);

        int t0 = tags[b * S + 0];
        float sc = st[t0] + d_emis[(size_t)(0 * B + b) * T + t0];
        int cnt = (ids[b * S + 0] != 0) ? 1 : 0;
        int prev = t0;
        for (int s = 1; s < S; s++) {
            int tg = tags[b * S + s];
            if (ids[b * S + s] != 0) {
                sc += Tr[prev * T + tg] + d_emis[(size_t)(s * B + b) * T + tg];
                cnt++;
            }
            prev = tg;
        }
        int se = cnt - 1; if (se < 0) se = 0;
        int lt = tags[b * S + se];
        d_llh[b] = sc + en[lt] - denom;
    }
}

__global__ void reduce_kernel(float* __restrict__ out)
{
    __shared__ float sh[128];
    int t = threadIdx.x;
    sh[t] = d_llh[t];
    __syncthreads();
    for (int o = 64; o; o >>= 1) {
        if (t < o) sh[t] += sh[t + o];
        __syncthreads();
    }
    if (t == 0) out[0] = sh[0] / 128.0f;
}

// ---------------- launch ----------------------------------------------------
extern "C" void kernel_launch(void* const* d_in, const int* in_sizes, int n_in,
                              void* d_out, int out_size)
{
    const int*   ids      = (const int*)d_in[0];
    const int*   tags     = (const int*)d_in[1];
    const float* emb      = (const float*)d_in[2];
    const float* w_ih_l0f = (const float*)d_in[3];
    const float* w_hh_l0f = (const float*)d_in[4];
    const float* b_l0f    = (const float*)d_in[5];
    const float* w_ih_l0b = (const float*)d_in[6];
    const float* w_hh_l0b = (const float*)d_in[7];
    const float* b_l0b    = (const float*)d_in[8];
    const float* w_ih_l1f = (const float*)d_in[9];
    const float* w_hh_l1f = (const float*)d_in[10];
    const float* b_l1f    = (const float*)d_in[11];
    const float* w_ih_l1b = (const float*)d_in[12];
    const float* w_hh_l1b = (const float*)d_in[13];
    const float* b_l1b    = (const float*)d_in[14];
    const float* fc_w     = (const float*)d_in[15];
    const float* fc_b     = (const float*)d_in[16];
    const float* cls_w    = (const float*)d_in[17];
    const float* cls_b    = (const float*)d_in[18];
    const float* trans    = (const float*)d_in[19];
    const float* st       = (const float*)d_in[20];
    const float* en       = (const float*)d_in[21];

    float *x0, *xpf, *xpb, *seq0, *seq1, *fcb, *hbuf, *cst;
    cudaGetSymbolAddress((void**)&x0,   d_x0);
    cudaGetSymbolAddress((void**)&xpf,  d_xpf);
    cudaGetSymbolAddress((void**)&xpb,  d_xpb);
    cudaGetSymbolAddress((void**)&seq0, d_seq0);
    cudaGetSymbolAddress((void**)&seq1, d_seq1);
    cudaGetSymbolAddress((void**)&fcb,  d_fc);
    cudaGetSymbolAddress((void**)&hbuf, d_hbuf);
    cudaGetSymbolAddress((void**)&cst,  d_cst);

    // 1) embedding
    embed_kernel<<<SB, 64>>>(ids, emb);

    // 2) layer-0 input projections (both directions)
    dim3 gproj(G4H / 128, SB / 128);
    sgemm_kernel<<<gproj, 256>>>(x0, w_ih_l0f, b_l0f, xpf, SB, G4H, E, 0);
    sgemm_kernel<<<gproj, 256>>>(x0, w_ih_l0b, b_l0b, xpb, SB, G4H, E, 0);

    // 3) layer-0 recurrence
    zero_states_kernel<<<512, 256>>>();
    for (int t = 0; t < S; t++) {
        lstm_step_kernel<<<dim3(H / 8, 2), 256>>>(
            xpf, xpb, w_hh_l0f, w_hh_l0b,
            hbuf + (size_t)(t & 1) * (2 * B * H),
            hbuf + (size_t)((t + 1) & 1) * (2 * B * H),
            cst, seq0, t);
    }

    // 4) layer-1 input projections
    sgemm_kernel<<<gproj, 256>>>(seq0, w_ih_l1f, b_l1f, xpf, SB, G4H, H2, 0);
    sgemm_kernel<<<gproj, 256>>>(seq0, w_ih_l1b, b_l1b, xpb, SB, G4H, H2, 0);

    // 5) layer-1 recurrence
    zero_states_kernel<<<512, 256>>>();
    for (int t = 0; t < S; t++) {
        lstm_step_kernel<<<dim3(H / 8, 2), 256>>>(
            xpf, xpb, w_hh_l1f, w_hh_l1b,
            hbuf + (size_t)(t & 1) * (2 * B * H),
            hbuf + (size_t)((t + 1) & 1) * (2 * B * H),
            cst, seq1, t);
    }

    // 6) FC + ReLU
    dim3 gfc(H / 128, SB / 128);
    sgemm_kernel<<<gfc, 256>>>(seq1, fc_w, fc_b, fcb, SB, H, H2, 1);

    // 7) emissions
    cls_kernel<<<SB, 256>>>(cls_w, cls_b);

    // 8) CRF + mean
    crf_kernel<<<B, 32>>>(ids, tags, trans, st, en);
    reduce_kernel<<<1, 128>>>((float*)d_out);
}

// round 3
// speedup vs baseline: 1.2802x; 1.2802x over previous
#include <cuda_runtime.h>
#include <cuda_bf16.h>
#include <cstdint>

// Problem constants
constexpr int S = 256, B = 128, E = 256, H = 512, T = 18;
constexpr int SB = S * B;          // 32768
constexpr int G4H = 4 * H;         // 2048
constexpr int H2 = 2 * H;          // 1024

// ---------------- scratch (static device globals; no allocation) ------------
__device__ float d_x0[SB * E];            // embedded input  [SB, E]
__device__ float d_xpf[(size_t)SB * G4H]; // forward input projection [SB, 4H]
__device__ float d_xpb[(size_t)SB * G4H]; // backward input projection
__device__ float d_seq0[(size_t)SB * H2]; // layer-0 output [SB, 2H]
__device__ float d_seq1[(size_t)SB * H2]; // layer-1 output
__device__ float d_fc[(size_t)SB * H];    // fc output [SB, H]
__device__ float d_emis[(size_t)SB * T];  // emissions [SB, T]
__device__ float d_hbuf[2][2 * B * H];    // h double buffer
__device__ float d_cst[2 * B * H];        // c state per dir
__device__ float d_llh[B];

// ---------------- helpers ---------------------------------------------------
__device__ __forceinline__ float sigm(float x) { return 1.f / (1.f + expf(-x)); }

__device__ __forceinline__ uint32_t f2tf32(float x) {
    uint32_t r;
    asm("cvt.rna.tf32.f32 %0, %1;" : "=r"(r) : "f"(x));
    return r;
}

// ---------------- embedding --------------------------------------------------
__global__ void embed_kernel(const int* __restrict__ ids, const float* __restrict__ emb)
{
    int row = blockIdx.x;            // = s*B + b
    int s = row / B, b = row - s * B;
    int id = ids[b * S + s];
    float4* dst = reinterpret_cast<float4*>(&d_x0[(size_t)row * E]);
    int e = threadIdx.x;             // 64 threads, E/4 = 64 float4
    if (id == 0) dst[e] = make_float4(0.f, 0.f, 0.f, 0.f);
    else dst[e] = reinterpret_cast<const float4*>(&emb[(size_t)id * E])[e];
}

// ---------------- TF32 tensor-core GEMM --------------------------------------
// C[M,N] = A[M,K] @ W[N,K]^T + bias, optional relu.
// Block tile 128x128, BK=16, 256 threads (8 warps), warp tile 64x32.
// mma.sync.aligned.m16n8k8.row.col.f32.tf32.tf32.f32
__global__ void __launch_bounds__(256) tf32_gemm_kernel(
    const float* __restrict__ A, const float* __restrict__ W,
    const float* __restrict__ bias, float* __restrict__ C,
    int M, int N, int K, int relu)
{
    __shared__ uint32_t As[16][136];   // k-major, padded (136 mod 32 = 8 -> conflict-free frag loads)
    __shared__ uint32_t Ws[16][136];

    int bm = blockIdx.y * 128, bn = blockIdx.x * 128;
    int tid  = threadIdx.x;
    int warp = tid >> 5, lane = tid & 31;
    int wm = (warp >> 2) * 64;         // warp row offset in tile (0/64)
    int wn = (warp & 3) * 32;          // warp col offset in tile (0/32/64/96)
    int lg = lane >> 2;                // group id 0..7
    int lt = lane & 3;                 // thread-in-group 0..3

    int lr = tid >> 2;                 // staging row 0..63
    int ls = tid & 3;                  // staging float4 seg

    const float* Ap = A + (size_t)(bm + lr) * K + ls * 4;
    const float* Wp = W + (size_t)(bn + lr) * K + ls * 4;
    const size_t arow2 = (size_t)64 * K;

    float4 pa0 = *reinterpret_cast<const float4*>(Ap);
    float4 pa1 = *reinterpret_cast<const float4*>(Ap + arow2);
    float4 pw0 = *reinterpret_cast<const float4*>(Wp);
    float4 pw1 = *reinterpret_cast<const float4*>(Wp + arow2);

    float acc[4][4][4] = {};           // [m-atom][n-atom][frag]

    for (int k0 = 0; k0 < K; k0 += 16) {
        // stage (with tf32 rounding)
        As[ls * 4 + 0][lr] = f2tf32(pa0.x); As[ls * 4 + 1][lr] = f2tf32(pa0.y);
        As[ls * 4 + 2][lr] = f2tf32(pa0.z); As[ls * 4 + 3][lr] = f2tf32(pa0.w);
        As[ls * 4 + 0][lr + 64] = f2tf32(pa1.x); As[ls * 4 + 1][lr + 64] = f2tf32(pa1.y);
        As[ls * 4 + 2][lr + 64] = f2tf32(pa1.z); As[ls * 4 + 3][lr + 64] = f2tf32(pa1.w);
        Ws[ls * 4 + 0][lr] = f2tf32(pw0.x); Ws[ls * 4 + 1][lr] = f2tf32(pw0.y);
        Ws[ls * 4 + 2][lr] = f2tf32(pw0.z); Ws[ls * 4 + 3][lr] = f2tf32(pw0.w);
        Ws[ls * 4 + 0][lr + 64] = f2tf32(pw1.x); Ws[ls * 4 + 1][lr + 64] = f2tf32(pw1.y);
        Ws[ls * 4 + 2][lr + 64] = f2tf32(pw1.z); Ws[ls * 4 + 3][lr + 64] = f2tf32(pw1.w);
        __syncthreads();

        if (k0 + 16 < K) {
            pa0 = *reinterpret_cast<const float4*>(Ap + k0 + 16);
            pa1 = *reinterpret_cast<const float4*>(Ap + arow2 + k0 + 16);
            pw0 = *reinterpret_cast<const float4*>(Wp + k0 + 16);
            pw1 = *reinterpret_cast<const float4*>(Wp + arow2 + k0 + 16);
        }

#pragma unroll
        for (int kk = 0; kk < 16; kk += 8) {
            uint32_t af[4][4], bf[4][2];
#pragma unroll
            for (int am = 0; am < 4; am++) {
                int r0 = wm + am * 16 + lg;
                af[am][0] = As[kk + lt][r0];
                af[am][1] = As[kk + lt][r0 + 8];
                af[am][2] = As[kk + lt + 4][r0];
                af[am][3] = As[kk + lt + 4][r0 + 8];
            }
#pragma unroll
            for (int an = 0; an < 4; an++) {
                int c0 = wn + an * 8 + lg;
                bf[an][0] = Ws[kk + lt][c0];
                bf[an][1] = Ws[kk + lt + 4][c0];
            }
#pragma unroll
            for (int am = 0; am < 4; am++)
#pragma unroll
                for (int an = 0; an < 4; an++) {
                    asm volatile(
                        "mma.sync.aligned.m16n8k8.row.col.f32.tf32.tf32.f32 "
                        "{%0,%1,%2,%3}, {%4,%5,%6,%7}, {%8,%9}, {%0,%1,%2,%3};"
                        : "+f"(acc[am][an][0]), "+f"(acc[am][an][1]),
                          "+f"(acc[am][an][2]), "+f"(acc[am][an][3])
                        : "r"(af[am][0]), "r"(af[am][1]), "r"(af[am][2]), "r"(af[am][3]),
                          "r"(bf[an][0]), "r"(bf[an][1]));
                }
        }
        __syncthreads();
    }

    // epilogue
#pragma unroll
    for (int am = 0; am < 4; am++) {
        int r0 = bm + wm + am * 16 + lg;
#pragma unroll
        for (int an = 0; an < 4; an++) {
            int c0 = bn + wn + an * 8 + lt * 2;
            float b0 = bias[c0], b1 = bias[c0 + 1];
            float v0 = acc[am][an][0] + b0;
            float v1 = acc[am][an][1] + b1;
            float v2 = acc[am][an][2] + b0;
            float v3 = acc[am][an][3] + b1;
            if (relu) {
                v0 = fmaxf(v0, 0.f); v1 = fmaxf(v1, 0.f);
                v2 = fmaxf(v2, 0.f); v3 = fmaxf(v3, 0.f);
            }
            *reinterpret_cast<float2*>(&C[(size_t)r0 * N + c0]) = make_float2(v0, v1);
            *reinterpret_cast<float2*>(&C[(size_t)(r0 + 8) * N + c0]) = make_float2(v2, v3);
        }
    }
}

// ---------------- zero h/c states -------------------------------------------
__global__ void zero_states_kernel()
{
    int i = blockIdx.x * 256 + threadIdx.x;
    if (i < 2 * B * H) {
        d_hbuf[0][i] = 0.f;
        d_hbuf[1][i] = 0.f;
        d_cst[i] = 0.f;
    }
}

// ---------------- fused LSTM step (both directions) -------------------------
__global__ void __launch_bounds__(256) lstm_step_kernel(
    const float* __restrict__ xpf, const float* __restrict__ xpb,
    const float* __restrict__ wf,  const float* __restrict__ wb,
    const float* __restrict__ hin, float* __restrict__ hout,
    float* __restrict__ cst, float* __restrict__ seq, int t)
{
    __shared__ float Hs[32][128];   // h chunk, k-major
    __shared__ float Ws[32][32];    // weight chunk, k-major
    int dir = blockIdx.y;
    int n0 = blockIdx.x * 8;
    int tt = dir ? (S - 1 - t) : t;
    const float* xp = dir ? xpb : xpf;
    const float* w  = dir ? wb : wf;
    const float* h  = hin  + dir * (B * H);
    float* hn       = hout + dir * (B * H);
    float* c        = cst  + dir * (B * H);

    int tid = threadIdx.x;
    int tx = tid & 15, ty = tid >> 4;
    int wnc = tid >> 3, wseg = tid & 7;                 // 32 cols x 8 segs
    int wr  = (wnc >> 3) * H + n0 + (wnc & 7);          // gate row in W_hh
    const float* wrow = w + (size_t)wr * H;

    float acc[8][2] = {};

    for (int k0 = 0; k0 < H; k0 += 32) {
#pragma unroll
        for (int i = 0; i < 4; i++) {
            int e = tid + i * 256;
            int m = e >> 3, seg = e & 7;
            float4 v = *reinterpret_cast<const float4*>(&h[m * H + k0 + seg * 4]);
            Hs[seg * 4 + 0][m] = v.x; Hs[seg * 4 + 1][m] = v.y;
            Hs[seg * 4 + 2][m] = v.z; Hs[seg * 4 + 3][m] = v.w;
        }
        {
            float4 v = *reinterpret_cast<const float4*>(&wrow[k0 + wseg * 4]);
            Ws[wseg * 4 + 0][wnc] = v.x; Ws[wseg * 4 + 1][wnc] = v.y;
            Ws[wseg * 4 + 2][wnc] = v.z; Ws[wseg * 4 + 3][wnc] = v.w;
        }
        __syncthreads();
#pragma unroll
        for (int k = 0; k < 32; k++) {
            float4 a0 = *reinterpret_cast<const float4*>(&Hs[k][ty * 8]);
            float4 a1 = *reinterpret_cast<const float4*>(&Hs[k][ty * 8 + 4]);
            float b0 = Ws[k][tx * 2], b1 = Ws[k][tx * 2 + 1];
            float a[8] = {a0.x, a0.y, a0.z, a0.w, a1.x, a1.y, a1.z, a1.w};
#pragma unroll
            for (int i = 0; i < 8; i++) {
                acc[i][0] += a[i] * b0;
                acc[i][1] += a[i] * b1;
            }
        }
        __syncthreads();
    }

    float* Gs = &Hs[0][0];
#pragma unroll
    for (int i = 0; i < 8; i++) {
        int m = ty * 8 + i;
#pragma unroll
        for (int j = 0; j < 2; j++) {
            int nc = tx * 2 + j;
            int r = (nc >> 3) * H + n0 + (nc & 7);
            Gs[m * 32 + nc] = acc[i][j] + xp[((size_t)tt * B + m) * G4H + r];
        }
    }
    __syncthreads();

    for (int e = tid; e < B * 8; e += 256) {
        int m = e >> 3, j = e & 7;
        float ig = Gs[m * 32 + j];
        float fg = Gs[m * 32 + 8 + j];
        float gg = Gs[m * 32 + 16 + j];
        float og = Gs[m * 32 + 24 + j];
        int idx = m * H + n0 + j;
        float cv = c[idx];
        float cn = sigm(fg) * cv + sigm(ig) * tanhf(gg);
        float hv = sigm(og) * tanhf(cn);
        c[idx] = cn;
        hn[idx] = hv;
        seq[((size_t)tt * B + m) * H2 + dir * H + n0 + j] = hv;
    }
}

// ---------------- classifier: emissions = fc @ cls_w^T + cls_b --------------
__global__ void cls_kernel(const float* __restrict__ clsw, const float* __restrict__ clsb)
{
    __shared__ float hrow[H];
    int row = blockIdx.x;
    int tid = threadIdx.x;   // 256
    reinterpret_cast<float2*>(hrow)[tid] =
        reinterpret_cast<const float2*>(&d_fc[(size_t)row * H])[tid];
    __syncthreads();
    int warp = tid >> 5, lane = tid & 31;
    for (int tg = warp; tg < T; tg += 8) {
        const float* wv = clsw + tg * H;
        float s = 0.f;
        for (int k = lane; k < H; k += 32) s += hrow[k] * wv[k];
#pragma unroll
        for (int o = 16; o; o >>= 1) s += __shfl_down_sync(0xffffffffu, s, o);
        if (lane == 0) d_emis[(size_t)row * T + tg] = s + clsb[tg];
    }
}

// ---------------- CRF -------------------------------------------------------
__global__ void crf_kernel(const int* __restrict__ ids, const int* __restrict__ tags,
                           const float* __restrict__ trans,
                           const float* __restrict__ st, const float* __restrict__ en)
{
    __shared__ float Tr[T * T];
    __shared__ float alpha[T];
    int b = blockIdx.x;
    int tid = threadIdx.x;   // 32
    for (int i = tid; i < T * T; i += 32) Tr[i] = trans[i];
    __syncthreads();

    if (tid < T) alpha[tid] = st[tid] + d_emis[(size_t)(0 * B + b) * T + tid];
    __syncthreads();
    for (int s = 1; s < S; s++) {
        bool msk = ids[b * S + s] != 0;
        float ns = 0.f;
        if (tid < T) {
            float mx = -1e30f;
#pragma unroll
            for (int i = 0; i < T; i++) mx = fmaxf(mx, alpha[i] + Tr[i * T + tid]);
            float sum = 0.f;
#pragma unroll
            for (int i = 0; i < T; i++) sum += expf(alpha[i] + Tr[i * T + tid] - mx);
            ns = mx + logf(sum) + d_emis[(size_t)(s * B + b) * T + tid];
        }
        __syncthreads();
        if (tid < T && msk) alpha[tid] = ns;
        __syncthreads();
    }

    if (tid == 0) {
        float mx = -1e30f;
        for (int i = 0; i < T; i++) mx = fmaxf(mx, alpha[i] + en[i]);
        float sum = 0.f;
        for (int i = 0; i < T; i++) sum += expf(alpha[i] + en[i] - mx);
        float denom = mx + logf(sum);

        int t0 = tags[b * S + 0];
        float sc = st[t0] + d_emis[(size_t)(0 * B + b) * T + t0];
        int cnt = (ids[b * S + 0] != 0) ? 1 : 0;
        int prev = t0;
        for (int s = 1; s < S; s++) {
            int tg = tags[b * S + s];
            if (ids[b * S + s] != 0) {
                sc += Tr[prev * T + tg] + d_emis[(size_t)(s * B + b) * T + tg];
                cnt++;
            }
            prev = tg;
        }
        int se = cnt - 1; if (se < 0) se = 0;
        int lt = tags[b * S + se];
        d_llh[b] = sc + en[lt] - denom;
    }
}

__global__ void reduce_kernel(float* __restrict__ out)
{
    __shared__ float sh[128];
    int t = threadIdx.x;
    sh[t] = d_llh[t];
    __syncthreads();
    for (int o = 64; o; o >>= 1) {
        if (t < o) sh[t] += sh[t + o];
        __syncthreads();
    }
    if (t == 0) out[0] = sh[0] / 128.0f;
}

// ---------------- launch ----------------------------------------------------
extern "C" void kernel_launch(void* const* d_in, const int* in_sizes, int n_in,
                              void* d_out, int out_size)
{
    const int*   ids      = (const int*)d_in[0];
    const int*   tags     = (const int*)d_in[1];
    const float* emb      = (const float*)d_in[2];
    const float* w_ih_l0f = (const float*)d_in[3];
    const float* w_hh_l0f = (const float*)d_in[4];
    const float* b_l0f    = (const float*)d_in[5];
    const float* w_ih_l0b = (const float*)d_in[6];
    const float* w_hh_l0b = (const float*)d_in[7];
    const float* b_l0b    = (const float*)d_in[8];
    const float* w_ih_l1f = (const float*)d_in[9];
    const float* w_hh_l1f = (const float*)d_in[10];
    const float* b_l1f    = (const float*)d_in[11];
    const float* w_ih_l1b = (const float*)d_in[12];
    const float* w_hh_l1b = (const float*)d_in[13];
    const float* b_l1b    = (const float*)d_in[14];
    const float* fc_w     = (const float*)d_in[15];
    const float* fc_b     = (const float*)d_in[16];
    const float* cls_w    = (const float*)d_in[17];
    const float* cls_b    = (const float*)d_in[18];
    const float* trans    = (const float*)d_in[19];
    const float* st       = (const float*)d_in[20];
    const float* en       = (const float*)d_in[21];

    float *x0, *xpf, *xpb, *seq0, *seq1, *fcb, *hbuf, *cst;
    cudaGetSymbolAddress((void**)&x0,   d_x0);
    cudaGetSymbolAddress((void**)&xpf,  d_xpf);
    cudaGetSymbolAddress((void**)&xpb,  d_xpb);
    cudaGetSymbolAddress((void**)&seq0, d_seq0);
    cudaGetSymbolAddress((void**)&seq1, d_seq1);
    cudaGetSymbolAddress((void**)&fcb,  d_fc);
    cudaGetSymbolAddress((void**)&hbuf, d_hbuf);
    cudaGetSymbolAddress((void**)&cst,  d_cst);

    // 1) embedding
    embed_kernel<<<SB, 64>>>(ids, emb);

    // 2) layer-0 input projections (both directions) — tensor cores
    dim3 gproj(G4H / 128, SB / 128);
    tf32_gemm_kernel<<<gproj, 256>>>(x0, w_ih_l0f, b_l0f, xpf, SB, G4H, E, 0);
    tf32_gemm_kernel<<<gproj, 256>>>(x0, w_ih_l0b, b_l0b, xpb, SB, G4H, E, 0);

    // 3) layer-0 recurrence
    zero_states_kernel<<<512, 256>>>();
    for (int t = 0; t < S; t++) {
        lstm_step_kernel<<<dim3(H / 8, 2), 256>>>(
            xpf, xpb, w_hh_l0f, w_hh_l0b,
            hbuf + (size_t)(t & 1) * (2 * B * H),
            hbuf + (size_t)((t + 1) & 1) * (2 * B * H),
            cst, seq0, t);
    }

    // 4) layer-1 input projections — tensor cores
    tf32_gemm_kernel<<<gproj, 256>>>(seq0, w_ih_l1f, b_l1f, xpf, SB, G4H, H2, 0);
    tf32_gemm_kernel<<<gproj, 256>>>(seq0, w_ih_l1b, b_l1b, xpb, SB, G4H, H2, 0);

    // 5) layer-1 recurrence
    zero_states_kernel<<<512, 256>>>();
    for (int t = 0; t < S; t++) {
        lstm_step_kernel<<<dim3(H / 8, 2), 256>>>(
            xpf, xpb, w_hh_l1f, w_hh_l1b,
            hbuf + (size_t)(t & 1) * (2 * B * H),
            hbuf + (size_t)((t + 1) & 1) * (2 * B * H),
            cst, seq1, t);
    }

    // 6) FC + ReLU — tensor cores
    dim3 gfc(H / 128, SB / 128);
    tf32_gemm_kernel<<<gfc, 256>>>(seq1, fc_w, fc_b, fcb, SB, H, H2, 1);

    // 7) emissions
    cls_kernel<<<SB, 256>>>(cls_w, cls_b);

    // 8) CRF + mean
    crf_kernel<<<B, 32>>>(ids, tags, trans, st, en);
    reduce_kernel<<<1, 128>>>((float*)d_out);
}